// round 1
// baseline (speedup 1.0000x reference)
#include <cuda_runtime.h>

#define NPG 50
#define EPG 400
#define NGRAPH 32768
#define NNODE (NGRAPH*NPG)
#define NEDGE (NGRAPH*EPG)
#define GPC 16          // graphs per CTA in the main kernel
#define T1 128
#define T2 256
#define G2 512
#define BN_EPS 1e-5f

// ---------------- device scratch (static; no allocation) ----------------
__device__ float g_G[NPG*16];      // folded fc1 for y = A^2 x path
__device__ float g_Gc[NPG*16];     // folded fc1 for r = A*1 (bias) path
__device__ float g_e1[16];         // constant bias into fc1
__device__ float g_sum1[16], g_ss1[16];
__device__ float g_W2p[16*32], g_c2[32];
__device__ float g_sum2[32], g_ss2[32];
__device__ float g_W3p[32*2], g_c3[2];
__device__ float g_a1[NGRAPH*16];  // 2 MB
__device__ float g_a2[NGRAPH*32];  // 4 MB

// ---------------- prep: fold W1k@W2k into fc1, zero accumulators ----------------
__global__ void prep_kernel(const float* __restrict__ W11, const float* __restrict__ b11,
                            const float* __restrict__ W21, const float* __restrict__ b21,
                            const float* __restrict__ W12, const float* __restrict__ b12,
                            const float* __restrict__ W22, const float* __restrict__ b22,
                            const float* __restrict__ W13, const float* __restrict__ b13,
                            const float* __restrict__ W23, const float* __restrict__ b23,
                            const float* __restrict__ fc1w, const float* __restrict__ fc1b)
{
    __shared__ float u[12], cv[12], dv[12];
    int tid = threadIdx.x;
    if (tid < 12) {
        int k = tid / 4, o = tid % 4;
        const float* W1 = (k==0) ? W11 : ((k==1) ? W12 : W13);
        const float* W2 = (k==0) ? W21 : ((k==1) ? W22 : W23);
        const float* b1 = (k==0) ? b11 : ((k==1) ? b12 : b13);
        const float* b2 = (k==0) ? b21 : ((k==1) ? b22 : b23);
        float uu = 0.f, cc = 0.f;
        #pragma unroll
        for (int m = 0; m < 4; ++m) { uu += W1[m]*W2[m*4+o]; cc += b1[m]*W2[m*4+o]; }
        u[tid] = uu; cv[tid] = cc; dv[tid] = b2[o];
    }
    __syncthreads();
    for (int i = tid; i < NPG*16; i += blockDim.x) {
        int j = i >> 4, o = i & 15;
        float gg = 0.f, gc = 0.f;
        #pragma unroll
        for (int f = 0; f < 12; ++f) {
            float w = fc1w[(j*12+f)*16 + o];
            gg += u[f]*w; gc += cv[f]*w;
        }
        g_G[i] = gg; g_Gc[i] = gc;
    }
    if (tid < 16) {
        float e = fc1b[tid];
        for (int j = 0; j < NPG; ++j)
            #pragma unroll
            for (int f = 0; f < 12; ++f)
                e += dv[f]*fc1w[(j*12+f)*16 + tid];
        g_e1[tid] = e;
        g_sum1[tid] = 0.f; g_ss1[tid] = 0.f;
    }
    if (tid < 32) { g_sum2[tid] = 0.f; g_ss2[tid] = 0.f; }
}

// ---------------- main GCN kernel: per-graph smem message passing ----------------
__global__ void __launch_bounds__(T1) gcn_kernel(const float* __restrict__ x,
                                                 const int* __restrict__ ei)
{
    __shared__ float sG[NPG*16], sGc[NPG*16], se1[16];
    __shared__ int   es[EPG], ed[EPG];
    __shared__ float dinv[NPG], tbuf[NPG], acc[NPG], yv[NPG], rv[NPG];
    int tid = threadIdx.x;
    for (int i = tid; i < NPG*16; i += T1) { sG[i] = g_G[i]; sGc[i] = g_Gc[i]; }
    if (tid < 16) se1[tid] = g_e1[tid];
    float psum = 0.f, pss = 0.f;
    int g0 = blockIdx.x * GPC;
    for (int gi = 0; gi < GPC; ++gi) {
        int g  = g0 + gi;
        int nb = g * NPG, eb = g * EPG;
        __syncthreads();
        for (int e = tid; e < EPG; e += T1) {
            es[e] = ei[eb + e] - nb;
            ed[e] = ei[NEDGE + eb + e] - nb;
        }
        if (tid < NPG) acc[tid] = 1.0f;                 // self-loop degree
        __syncthreads();
        for (int e = tid; e < EPG; e += T1) atomicAdd(&acc[ed[e]], 1.0f);
        __syncthreads();
        if (tid < NPG) dinv[tid] = rsqrtf(acc[tid]);
        // pass 1: x -> yv          (op(v) = D^-1/2 (A+I) D^-1/2 v)
        __syncthreads();
        if (tid < NPG) { float tv = x[nb+tid]*dinv[tid]; tbuf[tid] = tv; acc[tid] = tv; }
        __syncthreads();
        for (int e = tid; e < EPG; e += T1) atomicAdd(&acc[ed[e]], tbuf[es[e]]);
        __syncthreads();
        if (tid < NPG) yv[tid] = acc[tid]*dinv[tid];
        // pass 2: yv -> yv  (now yv = A^2 x)
        __syncthreads();
        if (tid < NPG) { float tv = yv[tid]*dinv[tid]; tbuf[tid] = tv; acc[tid] = tv; }
        __syncthreads();
        for (int e = tid; e < EPG; e += T1) atomicAdd(&acc[ed[e]], tbuf[es[e]]);
        __syncthreads();
        if (tid < NPG) yv[tid] = acc[tid]*dinv[tid];
        // pass 3: ones -> rv (row sums, carries GCN-layer biases; zero in this dataset)
        __syncthreads();
        if (tid < NPG) { float tv = dinv[tid]; tbuf[tid] = tv; acc[tid] = tv; }
        __syncthreads();
        for (int e = tid; e < EPG; e += T1) atomicAdd(&acc[ed[e]], tbuf[es[e]]);
        __syncthreads();
        if (tid < NPG) rv[tid] = acc[tid]*dinv[tid];
        __syncthreads();
        // fused fc1 + relu: a1[g, o] for o = tid < 16
        if (tid < 16) {
            float a = se1[tid];
            #pragma unroll 10
            for (int j = 0; j < NPG; ++j)
                a += yv[j]*sG[j*16+tid] + rv[j]*sGc[j*16+tid];
            a = fmaxf(a, 0.f);
            g_a1[g*16 + tid] = a;
            psum += a; pss += a*a;
        }
    }
    if (tid < 16) { atomicAdd(&g_sum1[tid], psum); atomicAdd(&g_ss1[tid], pss); }
}

// ---------------- fold BN1 into fc2 ----------------
__global__ void fold1_kernel(const float* __restrict__ fc2w, const float* __restrict__ fc2b,
                             const float* __restrict__ g1,   const float* __restrict__ bb1)
{
    __shared__ float s1[16], off[16];
    int tid = threadIdx.x;
    if (tid < 16) {
        float m = g_sum1[tid] * (1.0f/NGRAPH);
        float v = g_ss1[tid] * (1.0f/NGRAPH) - m*m;
        float sc = rsqrtf(v + BN_EPS) * g1[tid];
        s1[tid] = sc;
        off[tid] = bb1[tid] - m*sc;
    }
    __syncthreads();
    for (int i = tid; i < 16*32; i += blockDim.x)
        g_W2p[i] = s1[i >> 5] * fc2w[i];
    if (tid < 32) {
        float c = fc2b[tid];
        #pragma unroll
        for (int r = 0; r < 16; ++r) c += off[r]*fc2w[r*32+tid];
        g_c2[tid] = c;
    }
}

// ---------------- fc2 + relu + bn2 stats (one warp per row) ----------------
__global__ void __launch_bounds__(T2) fc2_kernel()
{
    __shared__ float sW[16*32], sc2[32], rsum[32], rss[32];
    int tid = threadIdx.x;
    for (int i = tid; i < 16*32; i += T2) sW[i] = g_W2p[i];
    if (tid < 32) { sc2[tid] = g_c2[tid]; rsum[tid] = 0.f; rss[tid] = 0.f; }
    __syncthreads();
    int lane = tid & 31;
    int warp = tid >> 5;
    float psum = 0.f, pss = 0.f;
    for (int b = blockIdx.x*(T2/32) + warp; b < NGRAPH; b += gridDim.x*(T2/32)) {
        const float* a1r = &g_a1[b*16];
        float z = sc2[lane];
        #pragma unroll
        for (int i = 0; i < 16; ++i) z += __ldg(&a1r[i]) * sW[i*32+lane];
        z = fmaxf(z, 0.f);
        g_a2[b*32 + lane] = z;
        psum += z; pss += z*z;
    }
    atomicAdd(&rsum[lane], psum);
    atomicAdd(&rss[lane], pss);
    __syncthreads();
    if (tid < 32) { atomicAdd(&g_sum2[tid], rsum[tid]); atomicAdd(&g_ss2[tid], rss[tid]); }
}

// ---------------- fold BN2 into fc3 ----------------
__global__ void fold2_kernel(const float* __restrict__ fc3w, const float* __restrict__ fc3b,
                             const float* __restrict__ g2,   const float* __restrict__ bb2)
{
    __shared__ float s2[32], off[32];
    int tid = threadIdx.x;
    if (tid < 32) {
        float m = g_sum2[tid] * (1.0f/NGRAPH);
        float v = g_ss2[tid] * (1.0f/NGRAPH) - m*m;
        float sc = rsqrtf(v + BN_EPS) * g2[tid];
        s2[tid] = sc;
        off[tid] = bb2[tid] - m*sc;
    }
    __syncthreads();
    if (tid < 64) g_W3p[tid] = s2[tid >> 1] * fc3w[tid];
    if (tid < 2) {
        float c = fc3b[tid];
        #pragma unroll
        for (int r = 0; r < 32; ++r) c += off[r]*fc3w[r*2+tid];
        g_c3[tid] = c;
    }
}

// ---------------- fc3: final logits ----------------
__global__ void __launch_bounds__(256) fc3_kernel(float* __restrict__ out)
{
    __shared__ float sW[64], sc3[2];
    int tid = threadIdx.x;
    if (tid < 64) sW[tid] = g_W3p[tid];
    if (tid < 2)  sc3[tid] = g_c3[tid];
    __syncthreads();
    int b = blockIdx.x*256 + tid;
    if (b >= NGRAPH) return;
    const float4* a2r = (const float4*)&g_a2[b*32];
    float o0 = sc3[0], o1 = sc3[1];
    #pragma unroll
    for (int q = 0; q < 8; ++q) {
        float4 v = a2r[q];
        o0 += v.x*sW[(q*4+0)*2]   + v.y*sW[(q*4+1)*2]   + v.z*sW[(q*4+2)*2]   + v.w*sW[(q*4+3)*2];
        o1 += v.x*sW[(q*4+0)*2+1] + v.y*sW[(q*4+1)*2+1] + v.z*sW[(q*4+2)*2+1] + v.w*sW[(q*4+3)*2+1];
    }
    ((float2*)out)[b] = make_float2(o0, o1);
}

// ---------------- launch ----------------
extern "C" void kernel_launch(void* const* d_in, const int* in_sizes, int n_in,
                              void* d_out, int out_size)
{
    const float* x    = (const float*)d_in[0];
    const int*   ei   = (const int*)  d_in[1];
    const float* W11  = (const float*)d_in[2];
    const float* b11  = (const float*)d_in[3];
    const float* W21  = (const float*)d_in[4];
    const float* b21  = (const float*)d_in[5];
    const float* W12  = (const float*)d_in[6];
    const float* b12  = (const float*)d_in[7];
    const float* W22  = (const float*)d_in[8];
    const float* b22  = (const float*)d_in[9];
    const float* W13  = (const float*)d_in[10];
    const float* b13  = (const float*)d_in[11];
    const float* W23  = (const float*)d_in[12];
    const float* b23  = (const float*)d_in[13];
    const float* fc1w = (const float*)d_in[14];
    const float* fc1b = (const float*)d_in[15];
    const float* bn1g = (const float*)d_in[16];
    const float* bn1b = (const float*)d_in[17];
    const float* fc2w = (const float*)d_in[18];
    const float* fc2b = (const float*)d_in[19];
    const float* bn2g = (const float*)d_in[20];
    const float* bn2b = (const float*)d_in[21];
    const float* fc3w = (const float*)d_in[22];
    const float* fc3b = (const float*)d_in[23];

    prep_kernel<<<1, 256>>>(W11,b11,W21,b21,W12,b12,W22,b22,W13,b13,W23,b23,fc1w,fc1b);
    gcn_kernel<<<NGRAPH/GPC, T1>>>(x, ei);
    fold1_kernel<<<1, 256>>>(fc2w, fc2b, bn1g, bn1b);
    fc2_kernel<<<G2, T2>>>();
    fold2_kernel<<<1, 64>>>(fc3w, fc3b, bn2g, bn2b);
    fc3_kernel<<<NGRAPH/256, 256>>>((float*)d_out);
}

// round 2
// speedup vs baseline: 1.3333x; 1.3333x over previous
#include <cuda_runtime.h>

#define NPG 50
#define EPG 400
#define NGRAPH 32768
#define NNODE (NGRAPH*NPG)
#define NEDGE (NGRAPH*EPG)
#define GPC 8            // graphs per CTA (amortizes sG/sGc load)
#define T1 128
#define PITCH 52         // padded row pitch for A (float4-aligned, low conflict)
#define BN_EPS 1e-5f

// ---------------- device scratch (static; no allocation) ----------------
__device__ float g_G[NPG*16];      // folded fc1 for yv = A^2 x path
__device__ float g_Gc[NPG*16];     // folded fc1 for rv = A*1 (GCN-bias) path
__device__ float g_e1[16];         // constant bias into fc1
__device__ float g_sum1[16], g_ss1[16];
__device__ float g_sum2[32], g_ss2[32];
__device__ float g_a1[NGRAPH*16];  // 2 MB
__device__ float g_a2[NGRAPH*32];  // 4 MB

// ---------------- prep: fold W1k@W2k into fc1, zero accumulators ----------------
__global__ void prep_kernel(const float* __restrict__ W11, const float* __restrict__ b11,
                            const float* __restrict__ W21, const float* __restrict__ b21,
                            const float* __restrict__ W12, const float* __restrict__ b12,
                            const float* __restrict__ W22, const float* __restrict__ b22,
                            const float* __restrict__ W13, const float* __restrict__ b13,
                            const float* __restrict__ W23, const float* __restrict__ b23,
                            const float* __restrict__ fc1w, const float* __restrict__ fc1b)
{
    __shared__ float u[12], cv[12], dv[12];
    int tid = threadIdx.x;
    if (tid < 12) {
        int k = tid / 4, o = tid % 4;
        const float* W1 = (k==0) ? W11 : ((k==1) ? W12 : W13);
        const float* W2 = (k==0) ? W21 : ((k==1) ? W22 : W23);
        const float* b1 = (k==0) ? b11 : ((k==1) ? b12 : b13);
        const float* b2 = (k==0) ? b21 : ((k==1) ? b22 : b23);
        float uu = 0.f, cc = 0.f;
        #pragma unroll
        for (int m = 0; m < 4; ++m) { uu += W1[m]*W2[m*4+o]; cc += b1[m]*W2[m*4+o]; }
        u[tid] = uu; cv[tid] = cc; dv[tid] = b2[o];
    }
    __syncthreads();
    for (int i = tid; i < NPG*16; i += blockDim.x) {
        int j = i >> 4, o = i & 15;
        float gg = 0.f, gc = 0.f;
        #pragma unroll
        for (int f = 0; f < 12; ++f) {
            float w = fc1w[(j*12+f)*16 + o];
            gg += u[f]*w; gc += cv[f]*w;
        }
        g_G[i] = gg; g_Gc[i] = gc;
    }
    if (tid < 16) {
        float e = fc1b[tid];
        for (int j = 0; j < NPG; ++j)
            #pragma unroll
            for (int f = 0; f < 12; ++f)
                e += dv[f]*fc1w[(j*12+f)*16 + tid];
        g_e1[tid] = e;
        g_sum1[tid] = 0.f; g_ss1[tid] = 0.f;
    }
    if (tid < 32) { g_sum2[tid] = 0.f; g_ss2[tid] = 0.f; }
}

// ---------------- main GCN kernel: dense per-graph adjacency in smem ----------------
__global__ void __launch_bounds__(T1) gcn_kernel(const float* __restrict__ x,
                                                 const int* __restrict__ ei)
{
    __shared__ float4 A4[NPG*PITCH/4];   // 10400 B dense adjacency (counts)
    __shared__ float2 wv[NPG];           // (dinv*x, dinv) for fused sweep 1
    __shared__ float  w2[NPG];           // prescaled input of sweep 2
    __shared__ float  yv[NPG], rv[NPG];
    __shared__ float  deg[NPG];
    __shared__ float  sG[NPG*16], sGc[NPG*16], se1[16];
    __shared__ float  pb[T1];
    float* A = (float*)A4;

    int tid = threadIdx.x;
    for (int i = tid; i < NPG*16; i += T1) { sG[i] = g_G[i]; sGc[i] = g_Gc[i]; }
    if (tid < 16) se1[tid] = g_e1[tid];
    float psum = 0.f, pss = 0.f;
    int g0 = blockIdx.x * GPC;

    for (int gi = 0; gi < GPC; ++gi) {
        int g  = g0 + gi;
        int nb = g * NPG, eb = g * EPG;
        __syncthreads();                     // protect A/deg/pb reuse
        // S0: zero A, init deg (self-loop), preload x into reg
        for (int i = tid; i < NPG*PITCH/4; i += T1) A4[i] = make_float4(0.f,0.f,0.f,0.f);
        float xv = 0.f, di = 0.f;
        if (tid < NPG) { deg[tid] = 1.0f; xv = x[nb + tid]; }
        __syncthreads();
        // S1: scatter edges into dense A + degree counts
        for (int e = tid; e < EPG; e += T1) {
            int s = ei[eb + e] - nb;
            int d = ei[NEDGE + eb + e] - nb;
            atomicAdd(&A[d*PITCH + s], 1.0f);
            atomicAdd(&deg[d], 1.0f);
        }
        __syncthreads();
        // S2: dinv, fused sweep-1 inputs
        if (tid < NPG) { di = rsqrtf(deg[tid]); wv[tid] = make_float2(xv*di, di); }
        __syncthreads();
        // S3: sweep 1 (fused x-pass and ones-pass): y = dinv*((A+I)w)
        if (tid < NPG) {
            float2 wt = wv[tid];
            float s1 = wt.x, sr = wt.y;                 // identity term
            const float4* Ar  = (const float4*)&A[tid*PITCH];
            const float4* wv4 = (const float4*)wv;
            #pragma unroll
            for (int q = 0; q < 12; ++q) {
                float4 a  = Ar[q];
                float4 p0 = wv4[2*q];
                float4 p1 = wv4[2*q+1];
                s1 += a.x*p0.x + a.y*p0.z + a.z*p1.x + a.w*p1.z;
                sr += a.x*p0.y + a.y*p0.w + a.z*p1.y + a.w*p1.w;
            }
            {
                float a48 = A[tid*PITCH+48], a49 = A[tid*PITCH+49];
                float2 q48 = wv[48], q49 = wv[49];
                s1 += a48*q48.x + a49*q49.x;
                sr += a48*q48.y + a49*q49.y;
            }
            w2[tid] = s1*di*di;      // prescale for sweep 2: dinv^2 * y1_raw
            rv[tid] = sr*di;
        }
        __syncthreads();
        // S4: sweep 2: yv = dinv*((A+I)w2)
        if (tid < NPG) {
            float s = w2[tid];
            const float4* Ar  = (const float4*)&A[tid*PITCH];
            const float4* w24 = (const float4*)w2;
            #pragma unroll
            for (int q = 0; q < 12; ++q) {
                float4 a = Ar[q];
                float4 w = w24[q];
                s += a.x*w.x + a.y*w.y + a.z*w.z + a.w*w.w;
            }
            s += A[tid*PITCH+48]*w2[48] + A[tid*PITCH+49]*w2[49];
            yv[tid] = s*di;
        }
        __syncthreads();
        // S5: fc1 partials (all 128 threads): a1[g,o] = e1 + sum_j yv[j]G[j,o] + rv[j]Gc[j,o]
        {
            int o = tid & 15, c = tid >> 4;
            float p = 0.f;
            for (int j = c; j < NPG; j += 8)
                p += yv[j]*sG[j*16+o] + rv[j]*sGc[j*16+o];
            pb[tid] = p;
        }
        __syncthreads();
        // S6: reduce + relu + store + BN1 stats
        if (tid < 16) {
            float a = se1[tid];
            #pragma unroll
            for (int c2 = 0; c2 < 8; ++c2) a += pb[c2*16 + tid];
            a = fmaxf(a, 0.f);
            g_a1[g*16 + tid] = a;
            psum += a; pss += a*a;
        }
    }
    if (tid < 16) { atomicAdd(&g_sum1[tid], psum); atomicAdd(&g_ss1[tid], pss); }
}

// ---------------- fc2: in-block BN1 fold + thread-per-graph GEMV + BN2 stats ----------------
__global__ void __launch_bounds__(256) fc2_kernel(const float* __restrict__ fc2w,
                                                  const float* __restrict__ fc2b,
                                                  const float* __restrict__ g1,
                                                  const float* __restrict__ bb1)
{
    __shared__ float sS[16], sOff[16];
    __shared__ float4 sW4[16*8];      // folded weights [16 in][32 out]
    __shared__ float sc2[32];
    __shared__ float rsum[32], rss[32];
    int tid = threadIdx.x;
    if (tid < 16) {
        float m = g_sum1[tid] * (1.0f/NGRAPH);
        float v = g_ss1[tid] * (1.0f/NGRAPH) - m*m;
        float sc = rsqrtf(v + BN_EPS) * g1[tid];
        sS[tid] = sc; sOff[tid] = bb1[tid] - m*sc;
    }
    if (tid < 32) { rsum[tid] = 0.f; rss[tid] = 0.f; }
    __syncthreads();
    float* sW = (float*)sW4;
    for (int i = tid; i < 512; i += 256) sW[i] = sS[i >> 5] * fc2w[i];
    if (tid < 32) {
        float c = fc2b[tid];
        #pragma unroll
        for (int r = 0; r < 16; ++r) c += sOff[r]*fc2w[r*32+tid];
        sc2[tid] = c;
    }
    __syncthreads();

    int b = blockIdx.x*256 + tid;
    const float4* a4 = (const float4*)&g_a1[b*16];
    float4 r0 = a4[0], r1 = a4[1], r2 = a4[2], r3 = a4[3];
    float a[16] = {r0.x,r0.y,r0.z,r0.w, r1.x,r1.y,r1.z,r1.w,
                   r2.x,r2.y,r2.z,r2.w, r3.x,r3.y,r3.z,r3.w};
    float z[32];
    float4* out4 = (float4*)&g_a2[b*32];
    #pragma unroll
    for (int o4 = 0; o4 < 8; ++o4) {
        float4 acc = make_float4(sc2[o4*4], sc2[o4*4+1], sc2[o4*4+2], sc2[o4*4+3]);
        #pragma unroll
        for (int i = 0; i < 16; ++i) {
            float4 w = sW4[i*8 + o4];
            acc.x += a[i]*w.x; acc.y += a[i]*w.y; acc.z += a[i]*w.z; acc.w += a[i]*w.w;
        }
        acc.x = fmaxf(acc.x, 0.f); acc.y = fmaxf(acc.y, 0.f);
        acc.z = fmaxf(acc.z, 0.f); acc.w = fmaxf(acc.w, 0.f);
        z[o4*4] = acc.x; z[o4*4+1] = acc.y; z[o4*4+2] = acc.z; z[o4*4+3] = acc.w;
        out4[o4] = acc;
    }
    // BN2 stats: warp shuffle reduce per output column
    int lane = tid & 31;
    float mysum = 0.f, myss = 0.f;
    #pragma unroll
    for (int o = 0; o < 32; ++o) {
        float r = z[o], q = z[o]*z[o];
        #pragma unroll
        for (int sh = 16; sh > 0; sh >>= 1) {
            r += __shfl_xor_sync(0xffffffffu, r, sh);
            q += __shfl_xor_sync(0xffffffffu, q, sh);
        }
        if (lane == o) { mysum = r; myss = q; }
    }
    atomicAdd(&rsum[lane], mysum);
    atomicAdd(&rss[lane], myss);
    __syncthreads();
    if (tid < 32) { atomicAdd(&g_sum2[tid], rsum[tid]); atomicAdd(&g_ss2[tid], rss[tid]); }
}

// ---------------- fc3: in-block BN2 fold + final logits ----------------
__global__ void __launch_bounds__(256) fc3_kernel(float* __restrict__ out,
                                                  const float* __restrict__ fc3w,
                                                  const float* __restrict__ fc3b,
                                                  const float* __restrict__ g2,
                                                  const float* __restrict__ bb2)
{
    __shared__ float sS[32], sOff[32], sW[64], sc3[2];
    int tid = threadIdx.x;
    if (tid < 32) {
        float m = g_sum2[tid] * (1.0f/NGRAPH);
        float v = g_ss2[tid] * (1.0f/NGRAPH) - m*m;
        float sc = rsqrtf(v + BN_EPS) * g2[tid];
        sS[tid] = sc; sOff[tid] = bb2[tid] - m*sc;
    }
    __syncthreads();
    if (tid < 64) sW[tid] = sS[tid >> 1] * fc3w[tid];
    if (tid < 2) {
        float c = fc3b[tid];
        #pragma unroll
        for (int r = 0; r < 32; ++r) c += sOff[r]*fc3w[r*2+tid];
        sc3[tid] = c;
    }
    __syncthreads();
    int b = blockIdx.x*256 + tid;
    const float4* a2r = (const float4*)&g_a2[b*32];
    float o0 = sc3[0], o1 = sc3[1];
    #pragma unroll
    for (int q = 0; q < 8; ++q) {
        float4 v = a2r[q];
        o0 += v.x*sW[(q*4+0)*2]   + v.y*sW[(q*4+1)*2]   + v.z*sW[(q*4+2)*2]   + v.w*sW[(q*4+3)*2];
        o1 += v.x*sW[(q*4+0)*2+1] + v.y*sW[(q*4+1)*2+1] + v.z*sW[(q*4+2)*2+1] + v.w*sW[(q*4+3)*2+1];
    }
    ((float2*)out)[b] = make_float2(o0, o1);
}

// ---------------- launch ----------------
extern "C" void kernel_launch(void* const* d_in, const int* in_sizes, int n_in,
                              void* d_out, int out_size)
{
    const float* x    = (const float*)d_in[0];
    const int*   ei   = (const int*)  d_in[1];
    const float* W11  = (const float*)d_in[2];
    const float* b11  = (const float*)d_in[3];
    const float* W21  = (const float*)d_in[4];
    const float* b21  = (const float*)d_in[5];
    const float* W12  = (const float*)d_in[6];
    const float* b12  = (const float*)d_in[7];
    const float* W22  = (const float*)d_in[8];
    const float* b22  = (const float*)d_in[9];
    const float* W13  = (const float*)d_in[10];
    const float* b13  = (const float*)d_in[11];
    const float* W23  = (const float*)d_in[12];
    const float* b23  = (const float*)d_in[13];
    const float* fc1w = (const float*)d_in[14];
    const float* fc1b = (const float*)d_in[15];
    const float* bn1g = (const float*)d_in[16];
    const float* bn1b = (const float*)d_in[17];
    const float* fc2w = (const float*)d_in[18];
    const float* fc2b = (const float*)d_in[19];
    const float* bn2g = (const float*)d_in[20];
    const float* bn2b = (const float*)d_in[21];
    const float* fc3w = (const float*)d_in[22];
    const float* fc3b = (const float*)d_in[23];

    prep_kernel<<<1, 256>>>(W11,b11,W21,b21,W12,b12,W22,b22,W13,b13,W23,b23,fc1w,fc1b);
    gcn_kernel<<<NGRAPH/GPC, T1>>>(x, ei);
    fc2_kernel<<<NGRAPH/256, 256>>>(fc2w, fc2b, bn1g, bn1b);
    fc3_kernel<<<NGRAPH/256, 256>>>((float*)d_out, fc3w, fc3b, bn2g, bn2b);
}

// round 3
// speedup vs baseline: 1.4556x; 1.0917x over previous
#include <cuda_runtime.h>

#define NPG 50
#define EPG 400
#define NGRAPH 32768
#define NNODE (NGRAPH*NPG)
#define NEDGE (NGRAPH*EPG)
#define GPC 8            // graphs per CTA
#define T1 128
#define PITCH 52         // floats per A row (float4-aligned)
#define BN_EPS 1e-5f

// ---------------- device scratch (static; no allocation) ----------------
__device__ float g_G[NPG*16];      // folded fc1 for yv = A^2 x path
__device__ float g_Gc[NPG*16];     // folded fc1 for rv = A*1 path
__device__ float g_e1[16];
__device__ float g_sum1[16], g_ss1[16];
__device__ float g_sum2[32], g_ss2[32];
__device__ float g_a1[NGRAPH*16];  // 2 MB
__device__ float g_a2[NGRAPH*32];  // 4 MB

// ---------------- prep: fold W1k@W2k into fc1, zero accumulators ----------------
__global__ void prep_kernel(const float* __restrict__ W11, const float* __restrict__ b11,
                            const float* __restrict__ W21, const float* __restrict__ b21,
                            const float* __restrict__ W12, const float* __restrict__ b12,
                            const float* __restrict__ W22, const float* __restrict__ b22,
                            const float* __restrict__ W13, const float* __restrict__ b13,
                            const float* __restrict__ W23, const float* __restrict__ b23,
                            const float* __restrict__ fc1w, const float* __restrict__ fc1b)
{
    __shared__ float u[12], cv[12], dv[12];
    int tid = threadIdx.x;
    if (tid < 12) {
        int k = tid / 4, o = tid % 4;
        const float* W1 = (k==0) ? W11 : ((k==1) ? W12 : W13);
        const float* W2 = (k==0) ? W21 : ((k==1) ? W22 : W23);
        const float* b1 = (k==0) ? b11 : ((k==1) ? b12 : b13);
        const float* b2 = (k==0) ? b21 : ((k==1) ? b22 : b23);
        float uu = 0.f, cc = 0.f;
        #pragma unroll
        for (int m = 0; m < 4; ++m) { uu += W1[m]*W2[m*4+o]; cc += b1[m]*W2[m*4+o]; }
        u[tid] = uu; cv[tid] = cc; dv[tid] = b2[o];
    }
    __syncthreads();
    for (int i = tid; i < NPG*16; i += blockDim.x) {
        int j = i >> 4, o = i & 15;
        float gg = 0.f, gc = 0.f;
        #pragma unroll
        for (int f = 0; f < 12; ++f) {
            float w = fc1w[(j*12+f)*16 + o];
            gg += u[f]*w; gc += cv[f]*w;
        }
        g_G[i] = gg; g_Gc[i] = gc;
    }
    if (tid < 16) {
        float e = fc1b[tid];
        for (int j = 0; j < NPG; ++j)
            #pragma unroll
            for (int f = 0; f < 12; ++f)
                e += dv[f]*fc1w[(j*12+f)*16 + tid];
        g_e1[tid] = e;
        g_sum1[tid] = 0.f; g_ss1[tid] = 0.f;
    }
    if (tid < 32) { g_sum2[tid] = 0.f; g_ss2[tid] = 0.f; }
}

// ---------------- main GCN kernel: tag-dedup dense adjacency, near-zero atomics ----------------
__global__ void __launch_bounds__(T1) gcn_kernel(const float* __restrict__ x,
                                                 const int* __restrict__ ei)
{
    __shared__ float4 A4[NPG*PITCH/4];      // 10.4 KB dense adjacency counts
    __shared__ unsigned short Atag[NPG*PITCH]; // 5.2 KB last-writer tags
    __shared__ float2 wv[NPG];
    __shared__ float  w2[NPG];
    __shared__ float  yv[NPG], rv[NPG];
    __shared__ float  sG[NPG*16], sGc[NPG*16], se1[16];
    __shared__ float  pb[T1];
    float* A = (float*)A4;

    int tid = threadIdx.x;
    for (int i = tid; i < NPG*16; i += T1) { sG[i] = g_G[i]; sGc[i] = g_Gc[i]; }
    if (tid < 16) se1[tid] = g_e1[tid];
    float psum = 0.f, pss = 0.f;
    int g0 = blockIdx.x * GPC;

    // prologue prefetch: graph g0 edges + x
    int ps[4], pd[4]; float pxv = 0.f;
    {
        int eb = g0 * EPG, nb = g0 * NPG;
        #pragma unroll
        for (int k = 0; k < 4; ++k) {
            int e = tid + k*T1;
            if (e < EPG) { ps[k] = ei[eb+e] - nb; pd[k] = ei[NEDGE+eb+e] - nb; }
        }
        if (tid < NPG) pxv = x[nb + tid];
    }

    for (int gi = 0; gi < GPC; ++gi) {
        int g = g0 + gi;
        int s[4], d[4]; float xv = pxv;
        #pragma unroll
        for (int k = 0; k < 4; ++k) { s[k] = ps[k]; d[k] = pd[k]; }

        __syncthreads();   // protect A/tags/pb reuse from previous graph
        // P0: zero A + write tags (disjoint arrays, no hazard)
        for (int i = tid; i < NPG*PITCH/4; i += T1) A4[i] = make_float4(0.f,0.f,0.f,0.f);
        #pragma unroll
        for (int k = 0; k < 4; ++k) {
            int e = tid + k*T1;
            if (e < EPG) Atag[d[k]*PITCH + s[k]] = (unsigned short)e;
        }
        __syncthreads();
        // P1: read tags -> ownership; owners write 1.0f; also prefetch next graph
        bool own[4];
        #pragma unroll
        for (int k = 0; k < 4; ++k) {
            int e = tid + k*T1;
            own[k] = false;
            if (e < EPG) {
                int cell = d[k]*PITCH + s[k];
                own[k] = (Atag[cell] == (unsigned short)e);
                if (own[k]) A[cell] = 1.0f;
            }
        }
        if (gi + 1 < GPC) {
            int eb = (g+1) * EPG, nb = (g+1) * NPG;
            #pragma unroll
            for (int k = 0; k < 4; ++k) {
                int e = tid + k*T1;
                if (e < EPG) { ps[k] = ei[eb+e] - nb; pd[k] = ei[NEDGE+eb+e] - nb; }
            }
            if (tid < NPG) pxv = x[nb + tid];
        }
        __syncthreads();
        // P2: duplicates only (expected ~30/graph) atomically bump counts
        #pragma unroll
        for (int k = 0; k < 4; ++k) {
            int e = tid + k*T1;
            if (e < EPG && !own[k]) atomicAdd(&A[d[k]*PITCH + s[k]], 1.0f);
        }
        __syncthreads();
        // P3: degree via row-sum, dinv, sweep-1 inputs
        float di = 0.f;
        if (tid < NPG) {
            const float4* Ar = (const float4*)&A[tid*PITCH];
            float dsum = 1.0f;   // self-loop
            #pragma unroll
            for (int q = 0; q < 12; ++q) {
                float4 a = Ar[q];
                dsum += a.x + a.y + a.z + a.w;
            }
            dsum += A[tid*PITCH+48] + A[tid*PITCH+49];
            di = rsqrtf(dsum);
            wv[tid] = make_float2(xv*di, di);
        }
        __syncthreads();
        // P4: sweep 1 (fused x-pass and ones-pass)
        if (tid < NPG) {
            float2 wt = wv[tid];
            float s1 = wt.x, sr = wt.y;          // identity term
            const float4* Ar  = (const float4*)&A[tid*PITCH];
            const float4* wv4 = (const float4*)wv;
            #pragma unroll
            for (int q = 0; q < 12; ++q) {
                float4 a  = Ar[q];
                float4 p0 = wv4[2*q];
                float4 p1 = wv4[2*q+1];
                s1 += a.x*p0.x + a.y*p0.z + a.z*p1.x + a.w*p1.z;
                sr += a.x*p0.y + a.y*p0.w + a.z*p1.y + a.w*p1.w;
            }
            {
                float a48 = A[tid*PITCH+48], a49 = A[tid*PITCH+49];
                float2 q48 = wv[48], q49 = wv[49];
                s1 += a48*q48.x + a49*q49.x;
                sr += a48*q48.y + a49*q49.y;
            }
            w2[tid] = s1*di*di;
            rv[tid] = sr*di;
        }
        __syncthreads();
        // P5: sweep 2
        if (tid < NPG) {
            float sacc = w2[tid];
            const float4* Ar  = (const float4*)&A[tid*PITCH];
            const float4* w24 = (const float4*)w2;
            #pragma unroll
            for (int q = 0; q < 12; ++q) {
                float4 a = Ar[q];
                float4 w = w24[q];
                sacc += a.x*w.x + a.y*w.y + a.z*w.z + a.w*w.w;
            }
            sacc += A[tid*PITCH+48]*w2[48] + A[tid*PITCH+49]*w2[49];
            yv[tid] = sacc*di;
        }
        __syncthreads();
        // P6: fc1 partials across all 128 threads
        {
            int o = tid & 15, c = tid >> 4;
            float p = 0.f;
            for (int j = c; j < NPG; j += 8)
                p += yv[j]*sG[j*16+o] + rv[j]*sGc[j*16+o];
            pb[tid] = p;
        }
        __syncthreads();
        // P7: reduce + relu + store + BN1 stats
        if (tid < 16) {
            float a = se1[tid];
            #pragma unroll
            for (int c2 = 0; c2 < 8; ++c2) a += pb[c2*16 + tid];
            a = fmaxf(a, 0.f);
            g_a1[g*16 + tid] = a;
            psum += a; pss += a*a;
        }
    }
    if (tid < 16) { atomicAdd(&g_sum1[tid], psum); atomicAdd(&g_ss1[tid], pss); }
}

// ---------------- fc2: in-block BN1 fold + thread-per-graph GEMV + BN2 stats ----------------
__global__ void __launch_bounds__(128) fc2_kernel(const float* __restrict__ fc2w,
                                                  const float* __restrict__ fc2b,
                                                  const float* __restrict__ g1,
                                                  const float* __restrict__ bb1)
{
    __shared__ float sS[16], sOff[16];
    __shared__ float4 sW4[16*8];
    __shared__ float sc2[32];
    __shared__ float rsum[32], rss[32];
    int tid = threadIdx.x;
    if (tid < 16) {
        float m = g_sum1[tid] * (1.0f/NGRAPH);
        float v = g_ss1[tid] * (1.0f/NGRAPH) - m*m;
        float sc = rsqrtf(v + BN_EPS) * g1[tid];
        sS[tid] = sc; sOff[tid] = bb1[tid] - m*sc;
    }
    if (tid < 32) { rsum[tid] = 0.f; rss[tid] = 0.f; }
    __syncthreads();
    float* sW = (float*)sW4;
    for (int i = tid; i < 512; i += 128) sW[i] = sS[i >> 5] * fc2w[i];
    if (tid < 32) {
        float c = fc2b[tid];
        #pragma unroll
        for (int r = 0; r < 16; ++r) c += sOff[r]*fc2w[r*32+tid];
        sc2[tid] = c;
    }
    __syncthreads();

    int b = blockIdx.x*128 + tid;
    const float4* a4 = (const float4*)&g_a1[b*16];
    float4 r0 = a4[0], r1 = a4[1], r2 = a4[2], r3 = a4[3];
    float a[16] = {r0.x,r0.y,r0.z,r0.w, r1.x,r1.y,r1.z,r1.w,
                   r2.x,r2.y,r2.z,r2.w, r3.x,r3.y,r3.z,r3.w};
    float z[32];
    float4* out4 = (float4*)&g_a2[b*32];
    #pragma unroll
    for (int o4 = 0; o4 < 8; ++o4) {
        float4 acc = make_float4(sc2[o4*4], sc2[o4*4+1], sc2[o4*4+2], sc2[o4*4+3]);
        #pragma unroll
        for (int i = 0; i < 16; ++i) {
            float4 w = sW4[i*8 + o4];
            acc.x += a[i]*w.x; acc.y += a[i]*w.y; acc.z += a[i]*w.z; acc.w += a[i]*w.w;
        }
        acc.x = fmaxf(acc.x, 0.f); acc.y = fmaxf(acc.y, 0.f);
        acc.z = fmaxf(acc.z, 0.f); acc.w = fmaxf(acc.w, 0.f);
        z[o4*4] = acc.x; z[o4*4+1] = acc.y; z[o4*4+2] = acc.z; z[o4*4+3] = acc.w;
        out4[o4] = acc;
    }
    // BN2 stats: warp shuffle reduce per output column
    int lane = tid & 31;
    float mysum = 0.f, myss = 0.f;
    #pragma unroll
    for (int o = 0; o < 32; ++o) {
        float r = z[o], q = z[o]*z[o];
        #pragma unroll
        for (int sh = 16; sh > 0; sh >>= 1) {
            r += __shfl_xor_sync(0xffffffffu, r, sh);
            q += __shfl_xor_sync(0xffffffffu, q, sh);
        }
        if (lane == o) { mysum = r; myss = q; }
    }
    atomicAdd(&rsum[lane], mysum);
    atomicAdd(&rss[lane], myss);
    __syncthreads();
    if (tid < 32) { atomicAdd(&g_sum2[tid], rsum[tid]); atomicAdd(&g_ss2[tid], rss[tid]); }
}

// ---------------- fc3: in-block BN2 fold + final logits ----------------
__global__ void __launch_bounds__(128) fc3_kernel(float* __restrict__ out,
                                                  const float* __restrict__ fc3w,
                                                  const float* __restrict__ fc3b,
                                                  const float* __restrict__ g2,
                                                  const float* __restrict__ bb2)
{
    __shared__ float sS[32], sOff[32], sW[64], sc3[2];
    int tid = threadIdx.x;
    if (tid < 32) {
        float m = g_sum2[tid] * (1.0f/NGRAPH);
        float v = g_ss2[tid] * (1.0f/NGRAPH) - m*m;
        float sc = rsqrtf(v + BN_EPS) * g2[tid];
        sS[tid] = sc; sOff[tid] = bb2[tid] - m*sc;
    }
    __syncthreads();
    if (tid < 64) sW[tid] = sS[tid >> 1] * fc3w[tid];
    if (tid < 2) {
        float c = fc3b[tid];
        #pragma unroll
        for (int r = 0; r < 32; ++r) c += sOff[r]*fc3w[r*2+tid];
        sc3[tid] = c;
    }
    __syncthreads();
    int b = blockIdx.x*128 + tid;
    const float4* a2r = (const float4*)&g_a2[b*32];
    float o0 = sc3[0], o1 = sc3[1];
    #pragma unroll
    for (int q = 0; q < 8; ++q) {
        float4 v = a2r[q];
        o0 += v.x*sW[(q*4+0)*2]   + v.y*sW[(q*4+1)*2]   + v.z*sW[(q*4+2)*2]   + v.w*sW[(q*4+3)*2];
        o1 += v.x*sW[(q*4+0)*2+1] + v.y*sW[(q*4+1)*2+1] + v.z*sW[(q*4+2)*2+1] + v.w*sW[(q*4+3)*2+1];
    }
    ((float2*)out)[b] = make_float2(o0, o1);
}

// ---------------- launch ----------------
extern "C" void kernel_launch(void* const* d_in, const int* in_sizes, int n_in,
                              void* d_out, int out_size)
{
    const float* x    = (const float*)d_in[0];
    const int*   ei   = (const int*)  d_in[1];
    const float* W11  = (const float*)d_in[2];
    const float* b11  = (const float*)d_in[3];
    const float* W21  = (const float*)d_in[4];
    const float* b21  = (const float*)d_in[5];
    const float* W12  = (const float*)d_in[6];
    const float* b12  = (const float*)d_in[7];
    const float* W22  = (const float*)d_in[8];
    const float* b22  = (const float*)d_in[9];
    const float* W13  = (const float*)d_in[10];
    const float* b13  = (const float*)d_in[11];
    const float* W23  = (const float*)d_in[12];
    const float* b23  = (const float*)d_in[13];
    const float* fc1w = (const float*)d_in[14];
    const float* fc1b = (const float*)d_in[15];
    const float* bn1g = (const float*)d_in[16];
    const float* bn1b = (const float*)d_in[17];
    const float* fc2w = (const float*)d_in[18];
    const float* fc2b = (const float*)d_in[19];
    const float* bn2g = (const float*)d_in[20];
    const float* bn2b = (const float*)d_in[21];
    const float* fc3w = (const float*)d_in[22];
    const float* fc3b = (const float*)d_in[23];

    prep_kernel<<<1, 256>>>(W11,b11,W21,b21,W12,b12,W22,b22,W13,b13,W23,b23,fc1w,fc1b);
    gcn_kernel<<<NGRAPH/GPC, T1>>>(x, ei);
    fc2_kernel<<<NGRAPH/128, 128>>>(fc2w, fc2b, bn1g, bn1b);
    fc3_kernel<<<NGRAPH/128, 128>>>((float*)d_out, fc3w, fc3b, bn2g, bn2b);
}

// round 4
// speedup vs baseline: 1.4632x; 1.0052x over previous
#include <cuda_runtime.h>

#define NPG 50
#define EPG 400
#define NGRAPH 32768
#define NNODE (NGRAPH*NPG)
#define NEDGE (NGRAPH*EPG)
#define GPC 8            // graphs per CTA
#define T1 128
#define PITCH 52         // floats per A row (float4-aligned)
#define BN_EPS 1e-5f

// ---------------- device scratch (static; no allocation) ----------------
__device__ float g_G[NPG*16];      // folded fc1 for yv = A^2 x path
__device__ float g_Gc[NPG*16];     // folded fc1 for rv = A*1 path
__device__ float g_e1[16];
__device__ float g_sum1[16], g_ss1[16];
__device__ float g_sum2[32], g_ss2[32];
__device__ float g_a1[NGRAPH*16];  // 2 MB
__device__ float g_a2[NGRAPH*32];  // 4 MB

// ---------------- prep: fold W1k@W2k into fc1, zero accumulators ----------------
__global__ void prep_kernel(const float* __restrict__ W11, const float* __restrict__ b11,
                            const float* __restrict__ W21, const float* __restrict__ b21,
                            const float* __restrict__ W12, const float* __restrict__ b12,
                            const float* __restrict__ W22, const float* __restrict__ b22,
                            const float* __restrict__ W13, const float* __restrict__ b13,
                            const float* __restrict__ W23, const float* __restrict__ b23,
                            const float* __restrict__ fc1w, const float* __restrict__ fc1b)
{
    __shared__ float u[12], cv[12], dv[12];
    int tid = threadIdx.x;
    if (tid < 12) {
        int k = tid / 4, o = tid % 4;
        const float* W1 = (k==0) ? W11 : ((k==1) ? W12 : W13);
        const float* W2 = (k==0) ? W21 : ((k==1) ? W22 : W23);
        const float* b1 = (k==0) ? b11 : ((k==1) ? b12 : b13);
        const float* b2 = (k==0) ? b21 : ((k==1) ? b22 : b23);
        float uu = 0.f, cc = 0.f;
        #pragma unroll
        for (int m = 0; m < 4; ++m) { uu += W1[m]*W2[m*4+o]; cc += b1[m]*W2[m*4+o]; }
        u[tid] = uu; cv[tid] = cc; dv[tid] = b2[o];
    }
    __syncthreads();
    for (int i = tid; i < NPG*16; i += blockDim.x) {
        int j = i >> 4, o = i & 15;
        float gg = 0.f, gc = 0.f;
        #pragma unroll
        for (int f = 0; f < 12; ++f) {
            float w = fc1w[(j*12+f)*16 + o];
            gg += u[f]*w; gc += cv[f]*w;
        }
        g_G[i] = gg; g_Gc[i] = gc;
    }
    if (tid < 16) {
        float e = fc1b[tid];
        for (int j = 0; j < NPG; ++j)
            #pragma unroll
            for (int f = 0; f < 12; ++f)
                e += dv[f]*fc1w[(j*12+f)*16 + tid];
        g_e1[tid] = e;
        g_sum1[tid] = 0.f; g_ss1[tid] = 0.f;
    }
    if (tid < 32) { g_sum2[tid] = 0.f; g_ss2[tid] = 0.f; }
}

// ---------------- main GCN kernel: tag-dedup dense adjacency, near-zero atomics ----------------
__global__ void __launch_bounds__(T1) gcn_kernel(const float* __restrict__ x,
                                                 const int* __restrict__ ei)
{
    __shared__ float4 A4[NPG*PITCH/4];      // 10.4 KB dense adjacency counts
    __shared__ unsigned short Atag[NPG*PITCH]; // 5.2 KB last-writer tags
    __shared__ float2 wv[NPG];
    __shared__ float  w2[NPG];
    __shared__ float  yv[NPG], rv[NPG];
    __shared__ float  sG[NPG*16], sGc[NPG*16], se1[16];
    __shared__ float  pb[T1];
    float* A = (float*)A4;

    int tid = threadIdx.x;
    for (int i = tid; i < NPG*16; i += T1) { sG[i] = g_G[i]; sGc[i] = g_Gc[i]; }
    if (tid < 16) se1[tid] = g_e1[tid];
    float psum = 0.f, pss = 0.f;
    int g0 = blockIdx.x * GPC;

    // prologue prefetch: graph g0 edges + x
    int ps[4], pd[4]; float pxv = 0.f;
    {
        int eb = g0 * EPG, nb = g0 * NPG;
        #pragma unroll
        for (int k = 0; k < 4; ++k) {
            int e = tid + k*T1;
            if (e < EPG) { ps[k] = ei[eb+e] - nb; pd[k] = ei[NEDGE+eb+e] - nb; }
        }
        if (tid < NPG) pxv = x[nb + tid];
    }

    for (int gi = 0; gi < GPC; ++gi) {
        int g = g0 + gi;
        int s[4], d[4]; float xv = pxv;
        #pragma unroll
        for (int k = 0; k < 4; ++k) { s[k] = ps[k]; d[k] = pd[k]; }

        __syncthreads();   // protect A/tags/pb reuse from previous graph
        // P0: zero A + write tags (disjoint arrays, no hazard)
        for (int i = tid; i < NPG*PITCH/4; i += T1) A4[i] = make_float4(0.f,0.f,0.f,0.f);
        #pragma unroll
        for (int k = 0; k < 4; ++k) {
            int e = tid + k*T1;
            if (e < EPG) Atag[d[k]*PITCH + s[k]] = (unsigned short)e;
        }
        __syncthreads();
        // P1: read tags -> ownership; owners write 1.0f; also prefetch next graph
        bool own[4];
        #pragma unroll
        for (int k = 0; k < 4; ++k) {
            int e = tid + k*T1;
            own[k] = false;
            if (e < EPG) {
                int cell = d[k]*PITCH + s[k];
                own[k] = (Atag[cell] == (unsigned short)e);
                if (own[k]) A[cell] = 1.0f;
            }
        }
        if (gi + 1 < GPC) {
            int eb = (g+1) * EPG, nb = (g+1) * NPG;
            #pragma unroll
            for (int k = 0; k < 4; ++k) {
                int e = tid + k*T1;
                if (e < EPG) { ps[k] = ei[eb+e] - nb; pd[k] = ei[NEDGE+eb+e] - nb; }
            }
            if (tid < NPG) pxv = x[nb + tid];
        }
        __syncthreads();
        // P2: duplicates only (expected ~30/graph) atomically bump counts
        #pragma unroll
        for (int k = 0; k < 4; ++k) {
            int e = tid + k*T1;
            if (e < EPG && !own[k]) atomicAdd(&A[d[k]*PITCH + s[k]], 1.0f);
        }
        __syncthreads();
        // P3: degree via row-sum, dinv, sweep-1 inputs
        float di = 0.f;
        if (tid < NPG) {
            const float4* Ar = (const float4*)&A[tid*PITCH];
            float dsum = 1.0f;   // self-loop
            #pragma unroll
            for (int q = 0; q < 12; ++q) {
                float4 a = Ar[q];
                dsum += a.x + a.y + a.z + a.w;
            }
            dsum += A[tid*PITCH+48] + A[tid*PITCH+49];
            di = rsqrtf(dsum);
            wv[tid] = make_float2(xv*di, di);
        }
        __syncthreads();
        // P4: sweep 1 (fused x-pass and ones-pass)
        if (tid < NPG) {
            float2 wt = wv[tid];
            float s1 = wt.x, sr = wt.y;          // identity term
            const float4* Ar  = (const float4*)&A[tid*PITCH];
            const float4* wv4 = (const float4*)wv;
            #pragma unroll
            for (int q = 0; q < 12; ++q) {
                float4 a  = Ar[q];
                float4 p0 = wv4[2*q];
                float4 p1 = wv4[2*q+1];
                s1 += a.x*p0.x + a.y*p0.z + a.z*p1.x + a.w*p1.z;
                sr += a.x*p0.y + a.y*p0.w + a.z*p1.y + a.w*p1.w;
            }
            {
                float a48 = A[tid*PITCH+48], a49 = A[tid*PITCH+49];
                float2 q48 = wv[48], q49 = wv[49];
                s1 += a48*q48.x + a49*q49.x;
                sr += a48*q48.y + a49*q49.y;
            }
            w2[tid] = s1*di*di;
            rv[tid] = sr*di;
        }
        __syncthreads();
        // P5: sweep 2
        if (tid < NPG) {
            float sacc = w2[tid];
            const float4* Ar  = (const float4*)&A[tid*PITCH];
            const float4* w24 = (const float4*)w2;
            #pragma unroll
            for (int q = 0; q < 12; ++q) {
                float4 a = Ar[q];
                float4 w = w24[q];
                sacc += a.x*w.x + a.y*w.y + a.z*w.z + a.w*w.w;
            }
            sacc += A[tid*PITCH+48]*w2[48] + A[tid*PITCH+49]*w2[49];
            yv[tid] = sacc*di;
        }
        __syncthreads();
        // P6: fc1 partials across all 128 threads
        {
            int o = tid & 15, c = tid >> 4;
            float p = 0.f;
            for (int j = c; j < NPG; j += 8)
                p += yv[j]*sG[j*16+o] + rv[j]*sGc[j*16+o];
            pb[tid] = p;
        }
        __syncthreads();
        // P7: reduce + relu + store + BN1 stats
        if (tid < 16) {
            float a = se1[tid];
            #pragma unroll
            for (int c2 = 0; c2 < 8; ++c2) a += pb[c2*16 + tid];
            a = fmaxf(a, 0.f);
            g_a1[g*16 + tid] = a;
            psum += a; pss += a*a;
        }
    }
    if (tid < 16) { atomicAdd(&g_sum1[tid], psum); atomicAdd(&g_ss1[tid], pss); }
}

// ---------------- fc2: in-block BN1 fold + thread-per-graph GEMV + BN2 stats ----------------
__global__ void __launch_bounds__(128) fc2_kernel(const float* __restrict__ fc2w,
                                                  const float* __restrict__ fc2b,
                                                  const float* __restrict__ g1,
                                                  const float* __restrict__ bb1)
{
    __shared__ float sS[16], sOff[16];
    __shared__ float4 sW4[16*8];
    __shared__ float sc2[32];
    __shared__ float rsum[32], rss[32];
    int tid = threadIdx.x;
    if (tid < 16) {
        float m = g_sum1[tid] * (1.0f/NGRAPH);
        float v = g_ss1[tid] * (1.0f/NGRAPH) - m*m;
        float sc = rsqrtf(v + BN_EPS) * g1[tid];
        sS[tid] = sc; sOff[tid] = bb1[tid] - m*sc;
    }
    if (tid < 32) { rsum[tid] = 0.f; rss[tid] = 0.f; }
    __syncthreads();
    float* sW = (float*)sW4;
    for (int i = tid; i < 512; i += 128) sW[i] = sS[i >> 5] * fc2w[i];
    if (tid < 32) {
        float c = fc2b[tid];
        #pragma unroll
        for (int r = 0; r < 16; ++r) c += sOff[r]*fc2w[r*32+tid];
        sc2[tid] = c;
    }
    __syncthreads();

    int b = blockIdx.x*128 + tid;
    const float4* a4 = (const float4*)&g_a1[b*16];
    float4 r0 = a4[0], r1 = a4[1], r2 = a4[2], r3 = a4[3];
    float a[16] = {r0.x,r0.y,r0.z,r0.w, r1.x,r1.y,r1.z,r1.w,
                   r2.x,r2.y,r2.z,r2.w, r3.x,r3.y,r3.z,r3.w};
    float z[32];
    float4* out4 = (float4*)&g_a2[b*32];
    #pragma unroll
    for (int o4 = 0; o4 < 8; ++o4) {
        float4 acc = make_float4(sc2[o4*4], sc2[o4*4+1], sc2[o4*4+2], sc2[o4*4+3]);
        #pragma unroll
        for (int i = 0; i < 16; ++i) {
            float4 w = sW4[i*8 + o4];
            acc.x += a[i]*w.x; acc.y += a[i]*w.y; acc.z += a[i]*w.z; acc.w += a[i]*w.w;
        }
        acc.x = fmaxf(acc.x, 0.f); acc.y = fmaxf(acc.y, 0.f);
        acc.z = fmaxf(acc.z, 0.f); acc.w = fmaxf(acc.w, 0.f);
        z[o4*4] = acc.x; z[o4*4+1] = acc.y; z[o4*4+2] = acc.z; z[o4*4+3] = acc.w;
        out4[o4] = acc;
    }
    // BN2 stats: warp shuffle reduce per output column
    int lane = tid & 31;
    float mysum = 0.f, myss = 0.f;
    #pragma unroll
    for (int o = 0; o < 32; ++o) {
        float r = z[o], q = z[o]*z[o];
        #pragma unroll
        for (int sh = 16; sh > 0; sh >>= 1) {
            r += __shfl_xor_sync(0xffffffffu, r, sh);
            q += __shfl_xor_sync(0xffffffffu, q, sh);
        }
        if (lane == o) { mysum = r; myss = q; }
    }
    atomicAdd(&rsum[lane], mysum);
    atomicAdd(&rss[lane], myss);
    __syncthreads();
    if (tid < 32) { atomicAdd(&g_sum2[tid], rsum[tid]); atomicAdd(&g_ss2[tid], rss[tid]); }
}

// ---------------- fc3: in-block BN2 fold + final logits ----------------
__global__ void __launch_bounds__(128) fc3_kernel(float* __restrict__ out,
                                                  const float* __restrict__ fc3w,
                                                  const float* __restrict__ fc3b,
                                                  const float* __restrict__ g2,
                                                  const float* __restrict__ bb2)
{
    __shared__ float sS[32], sOff[32], sW[64], sc3[2];
    int tid = threadIdx.x;
    if (tid < 32) {
        float m = g_sum2[tid] * (1.0f/NGRAPH);
        float v = g_ss2[tid] * (1.0f/NGRAPH) - m*m;
        float sc = rsqrtf(v + BN_EPS) * g2[tid];
        sS[tid] = sc; sOff[tid] = bb2[tid] - m*sc;
    }
    __syncthreads();
    if (tid < 64) sW[tid] = sS[tid >> 1] * fc3w[tid];
    if (tid < 2) {
        float c = fc3b[tid];
        #pragma unroll
        for (int r = 0; r < 32; ++r) c += sOff[r]*fc3w[r*2+tid];
        sc3[tid] = c;
    }
    __syncthreads();
    int b = blockIdx.x*128 + tid;
    const float4* a2r = (const float4*)&g_a2[b*32];
    float o0 = sc3[0], o1 = sc3[1];
    #pragma unroll
    for (int q = 0; q < 8; ++q) {
        float4 v = a2r[q];
        o0 += v.x*sW[(q*4+0)*2]   + v.y*sW[(q*4+1)*2]   + v.z*sW[(q*4+2)*2]   + v.w*sW[(q*4+3)*2];
        o1 += v.x*sW[(q*4+0)*2+1] + v.y*sW[(q*4+1)*2+1] + v.z*sW[(q*4+2)*2+1] + v.w*sW[(q*4+3)*2+1];
    }
    ((float2*)out)[b] = make_float2(o0, o1);
}

// ---------------- launch ----------------
extern "C" void kernel_launch(void* const* d_in, const int* in_sizes, int n_in,
                              void* d_out, int out_size)
{
    const float* x    = (const float*)d_in[0];
    const int*   ei   = (const int*)  d_in[1];
    const float* W11  = (const float*)d_in[2];
    const float* b11  = (const float*)d_in[3];
    const float* W21  = (const float*)d_in[4];
    const float* b21  = (const float*)d_in[5];
    const float* W12  = (const float*)d_in[6];
    const float* b12  = (const float*)d_in[7];
    const float* W22  = (const float*)d_in[8];
    const float* b22  = (const float*)d_in[9];
    const float* W13  = (const float*)d_in[10];
    const float* b13  = (const float*)d_in[11];
    const float* W23  = (const float*)d_in[12];
    const float* b23  = (const float*)d_in[13];
    const float* fc1w = (const float*)d_in[14];
    const float* fc1b = (const float*)d_in[15];
    const float* bn1g = (const float*)d_in[16];
    const float* bn1b = (const float*)d_in[17];
    const float* fc2w = (const float*)d_in[18];
    const float* fc2b = (const float*)d_in[19];
    const float* bn2g = (const float*)d_in[20];
    const float* bn2b = (const float*)d_in[21];
    const float* fc3w = (const float*)d_in[22];
    const float* fc3b = (const float*)d_in[23];

    prep_kernel<<<1, 256>>>(W11,b11,W21,b21,W12,b12,W22,b22,W13,b13,W23,b23,fc1w,fc1b);
    gcn_kernel<<<NGRAPH/GPC, T1>>>(x, ei);
    fc2_kernel<<<NGRAPH/128, 128>>>(fc2w, fc2b, bn1g, bn1b);
    fc3_kernel<<<NGRAPH/128, 128>>>((float*)d_out, fc3w, fc3b, bn2g, bn2b);
}

// round 5
// speedup vs baseline: 1.4901x; 1.0183x over previous
#include <cuda_runtime.h>

typedef unsigned long long u64;

#define NPG 50
#define EPG 400
#define NGRAPH 32768
#define NNODE (NGRAPH*NPG)
#define NEDGE (NGRAPH*EPG)
#define PAIRS 4           // graph-pairs per CTA (8 graphs)
#define T1 128
#define PITCH2 54         // float2 columns per A row (50 data + 4 pad)
#define BN_EPS 1e-5f

#define FMA2(acc,a,b) asm("fma.rn.f32x2 %0,%1,%2,%0;" : "+l"(acc) : "l"(a), "l"(b))
#define ADD2(acc,a)   asm("add.rn.f32x2 %0,%1,%0;"    : "+l"(acc) : "l"(a))
__device__ __forceinline__ u64 packf2(float lo, float hi) {
    u64 r; asm("mov.b64 %0,{%1,%2};" : "=l"(r) : "r"(__float_as_uint(lo)), "r"(__float_as_uint(hi)));
    return r;
}
__device__ __forceinline__ u64 dupf2(float v) {
    u64 r; asm("mov.b64 %0,{%1,%1};" : "=l"(r) : "r"(__float_as_uint(v)));
    return r;
}
__device__ __forceinline__ float lo32(u64 v){ return __uint_as_float((unsigned)v); }
__device__ __forceinline__ float hi32(u64 v){ return __uint_as_float((unsigned)(v>>32)); }

// ---------------- device scratch (static; no allocation) ----------------
__device__ float g_G[NPG*16];      // folded fc1 for yv = A^2 x path
__device__ float g_Gc[NPG*16];     // folded fc1 for rv = A*1 path
__device__ float g_e1[16];
__device__ float g_sum1[16], g_ss1[16];
__device__ float g_sum2[32], g_ss2[32];
__device__ float g_a1[NGRAPH*16];  // 2 MB

// ---------------- prep: fold W1k@W2k into fc1, zero accumulators ----------------
__global__ void prep_kernel(const float* __restrict__ W11, const float* __restrict__ b11,
                            const float* __restrict__ W21, const float* __restrict__ b21,
                            const float* __restrict__ W12, const float* __restrict__ b12,
                            const float* __restrict__ W22, const float* __restrict__ b22,
                            const float* __restrict__ W13, const float* __restrict__ b13,
                            const float* __restrict__ W23, const float* __restrict__ b23,
                            const float* __restrict__ fc1w, const float* __restrict__ fc1b)
{
    __shared__ float u[12], cv[12], dv[12];
    int tid = threadIdx.x;
    if (tid < 12) {
        int k = tid / 4, o = tid % 4;
        const float* W1 = (k==0) ? W11 : ((k==1) ? W12 : W13);
        const float* W2 = (k==0) ? W21 : ((k==1) ? W22 : W23);
        const float* b1 = (k==0) ? b11 : ((k==1) ? b12 : b13);
        const float* b2 = (k==0) ? b21 : ((k==1) ? b22 : b23);
        float uu = 0.f, cc = 0.f;
        #pragma unroll
        for (int m = 0; m < 4; ++m) { uu += W1[m]*W2[m*4+o]; cc += b1[m]*W2[m*4+o]; }
        u[tid] = uu; cv[tid] = cc; dv[tid] = b2[o];
    }
    __syncthreads();
    for (int i = tid; i < NPG*16; i += blockDim.x) {
        int j = i >> 4, o = i & 15;
        float gg = 0.f, gc = 0.f;
        #pragma unroll
        for (int f = 0; f < 12; ++f) {
            float w = fc1w[(j*12+f)*16 + o];
            gg += u[f]*w; gc += cv[f]*w;
        }
        g_G[i] = gg; g_Gc[i] = gc;
    }
    if (tid < 16) {
        float e = fc1b[tid];
        for (int j = 0; j < NPG; ++j)
            #pragma unroll
            for (int f = 0; f < 12; ++f)
                e += dv[f]*fc1w[(j*12+f)*16 + tid];
        g_e1[tid] = e;
        g_sum1[tid] = 0.f; g_ss1[tid] = 0.f;
    }
    if (tid < 32) { g_sum2[tid] = 0.f; g_ss2[tid] = 0.f; }
}

// ---------------- main GCN kernel: paired graphs, f32x2 packed sweeps ----------------
__global__ void __launch_bounds__(T1) gcn_kernel(const float* __restrict__ x,
                                                 const int* __restrict__ ei)
{
    __shared__ __align__(16) float A2f[NPG*PITCH2*2];   // 21.6 KB: float2 cells
    __shared__ unsigned short tagP[2*NPG*PITCH2];       // 10.8 KB
    __shared__ __align__(16) float2 wxp[PITCH2];        // (x̂A, x̂B), pads 0
    __shared__ __align__(16) float2 wdp[PITCH2];        // (d̂A, d̂B), pads 0
    __shared__ __align__(16) float2 w2p[PITCH2];        // sweep-2 input, pads 0
    __shared__ u64 yv2[NPG], rv2[NPG];
    __shared__ float sG[NPG*16], sGc[NPG*16], se1[16];
    __shared__ u64 pb[T1];

    int tid = threadIdx.x;
    for (int i = tid; i < NPG*16; i += T1) { sG[i] = g_G[i]; sGc[i] = g_Gc[i]; }
    if (tid < 16) se1[tid] = g_e1[tid];
    if (tid >= NPG && tid < PITCH2) {    // zero pads once (tid 50..53)
        wxp[tid] = make_float2(0.f,0.f);
        wdp[tid] = make_float2(0.f,0.f);
        w2p[tid] = make_float2(0.f,0.f);
    }
    float psum = 0.f, pss = 0.f;
    int gA0 = blockIdx.x * (2*PAIRS);

    // prologue prefetch: pair 0 edges (800 contiguous) + x (100 nodes)
    int ps[7], pd[7]; float pxA = 0.f, pxB = 0.f;
    {
        int eb = gA0 * EPG, nbA = gA0 * NPG;
        #pragma unroll
        for (int k = 0; k < 7; ++k) {
            int e = tid + k*T1;
            if (e < 2*EPG) { ps[k] = ei[eb+e] - nbA; pd[k] = ei[NEDGE+eb+e] - nbA; }
        }
        if (tid < NPG) { pxA = x[nbA + tid]; pxB = x[nbA + NPG + tid]; }
    }

    for (int pi = 0; pi < PAIRS; ++pi) {
        int gA = gA0 + 2*pi;
        // P0: zero A + write tags
        float4* A4 = (float4*)A2f;
        for (int i = tid; i < NPG*PITCH2*2/4; i += T1) A4[i] = make_float4(0.f,0.f,0.f,0.f);
        int ci[7], ti[7];
        #pragma unroll
        for (int k = 0; k < 7; ++k) {
            int e = tid + k*T1;
            ci[k] = -1;
            if (e < 2*EPG) {
                int kb = (e >= EPG);
                int srow = ps[k] - NPG*kb;
                int drow = pd[k] - NPG*kb;
                int cell = drow*PITCH2 + srow;
                ci[k] = cell*2 + kb;
                ti[k] = kb*(NPG*PITCH2) + cell;
                tagP[ti[k]] = (unsigned short)(e - EPG*kb);
            }
        }
        __syncthreads();                                   // B1
        // P1: ownership; owners write 1.0; prefetch next pair
        bool own[7];
        #pragma unroll
        for (int k = 0; k < 7; ++k) {
            own[k] = false;
            if (ci[k] >= 0) {
                int e = tid + k*T1;
                int kb = (e >= EPG);
                own[k] = (tagP[ti[k]] == (unsigned short)(e - EPG*kb));
                if (own[k]) A2f[ci[k]] = 1.0f;
            }
        }
        float xA = pxA, xB = pxB;
        if (pi + 1 < PAIRS) {
            int eb = (gA+2) * EPG, nbA = (gA+2) * NPG;
            #pragma unroll
            for (int k = 0; k < 7; ++k) {
                int e = tid + k*T1;
                if (e < 2*EPG) { ps[k] = ei[eb+e] - nbA; pd[k] = ei[NEDGE+eb+e] - nbA; }
            }
            if (tid < NPG) { pxA = x[nbA + tid]; pxB = x[nbA + NPG + tid]; }
        }
        __syncthreads();                                   // B2
        // P2: duplicates only
        #pragma unroll
        for (int k = 0; k < 7; ++k)
            if (ci[k] >= 0 && !own[k]) atomicAdd(&A2f[ci[k]], 1.0f);
        __syncthreads();                                   // B3
        // P3: rowsum -> dinv pair; sweep-1 inputs
        float diA = 0.f, diB = 0.f;
        const ulonglong2* Ar = (const ulonglong2*)&A2f[tid*PITCH2*2];
        if (tid < NPG) {
            u64 d0 = 0x3F8000003F800000ULL, d1 = 0;       // (1,1) self-loop
            #pragma unroll
            for (int q = 0; q < PITCH2/2; ++q) {
                ulonglong2 a = Ar[q];
                ADD2(d0, a.x); ADD2(d1, a.y);
            }
            ADD2(d0, d1);
            diA = rsqrtf(lo32(d0)); diB = rsqrtf(hi32(d0));
            wxp[tid] = make_float2(xA*diA, xB*diB);
            wdp[tid] = make_float2(diA, diB);
        }
        __syncthreads();                                   // B4
        // P4: sweep 1 (x-path and ones-path fused, both graphs packed)
        if (tid < NPG) {
            u64 ax0 = *(const u64*)&wxp[tid], ax1 = 0;     // identity terms
            u64 ar0 = *(const u64*)&wdp[tid], ar1 = 0;
            const ulonglong2* wx4 = (const ulonglong2*)wxp;
            const ulonglong2* wd4 = (const ulonglong2*)wdp;
            #pragma unroll
            for (int q = 0; q < PITCH2/2; ++q) {
                ulonglong2 a = Ar[q];
                ulonglong2 wx = wx4[q];
                ulonglong2 wd = wd4[q];
                FMA2(ax0, a.x, wx.x); FMA2(ax1, a.y, wx.y);
                FMA2(ar0, a.x, wd.x); FMA2(ar1, a.y, wd.y);
            }
            ADD2(ax0, ax1); ADD2(ar0, ar1);
            w2p[tid] = make_float2(lo32(ax0)*diA*diA, hi32(ax0)*diB*diB);
            rv2[tid] = packf2(lo32(ar0)*diA, hi32(ar0)*diB);
        }
        __syncthreads();                                   // B5
        // P5: sweep 2
        if (tid < NPG) {
            u64 s0 = *(const u64*)&w2p[tid], s1 = 0;       // identity term
            const ulonglong2* w24 = (const ulonglong2*)w2p;
            #pragma unroll
            for (int q = 0; q < PITCH2/2; ++q) {
                ulonglong2 a = Ar[q];
                ulonglong2 w = w24[q];
                FMA2(s0, a.x, w.x); FMA2(s1, a.y, w.y);
            }
            ADD2(s0, s1);
            yv2[tid] = packf2(lo32(s0)*diA, hi32(s0)*diB);
        }
        __syncthreads();                                   // B6
        // P6: fc1 partials, both graphs packed
        {
            int o = tid & 15, c = tid >> 4;
            u64 p = 0;
            for (int j = c; j < NPG; j += 8) {
                u64 y = yv2[j], r = rv2[j];
                u64 gd  = dupf2(sG [j*16+o]);
                u64 gcd = dupf2(sGc[j*16+o]);
                FMA2(p, y, gd);
                FMA2(p, r, gcd);
            }
            pb[tid] = p;
        }
        __syncthreads();                                   // B7
        // P7: reduce + relu + store a1 for both graphs + BN1 stats
        if (tid < 16) {
            u64 acc = dupf2(se1[tid]);
            #pragma unroll
            for (int c2 = 0; c2 < 8; ++c2) ADD2(acc, pb[c2*16 + tid]);
            float aA = fmaxf(lo32(acc), 0.f);
            float aB = fmaxf(hi32(acc), 0.f);
            g_a1[gA*16 + tid]     = aA;
            g_a1[(gA+1)*16 + tid] = aB;
            psum += aA + aB; pss += aA*aA + aB*aB;
        }
        // no barrier needed: next P0 touches only A/tags (last read before B6/B2)
    }
    if (tid < 16) { atomicAdd(&g_sum1[tid], psum); atomicAdd(&g_ss1[tid], pss); }
}

// ---------------- fc2 stats-only: BN1 fold + GEMV + relu -> BN2 sums ----------------
__global__ void __launch_bounds__(128) fc2_kernel(const float* __restrict__ fc2w,
                                                  const float* __restrict__ fc2b,
                                                  const float* __restrict__ g1,
                                                  const float* __restrict__ bb1)
{
    __shared__ float sS[16], sOff[16];
    __shared__ float4 sW4[16*8];
    __shared__ float sc2[32];
    __shared__ float rsum[32], rss[32];
    int tid = threadIdx.x;
    if (tid < 16) {
        float m = g_sum1[tid] * (1.0f/NGRAPH);
        float v = g_ss1[tid] * (1.0f/NGRAPH) - m*m;
        float sc = rsqrtf(v + BN_EPS) * g1[tid];
        sS[tid] = sc; sOff[tid] = bb1[tid] - m*sc;
    }
    if (tid < 32) { rsum[tid] = 0.f; rss[tid] = 0.f; }
    __syncthreads();
    float* sW = (float*)sW4;
    for (int i = tid; i < 512; i += 128) sW[i] = sS[i >> 5] * fc2w[i];
    if (tid < 32) {
        float c = fc2b[tid];
        #pragma unroll
        for (int r = 0; r < 16; ++r) c += sOff[r]*fc2w[r*32+tid];
        sc2[tid] = c;
    }
    __syncthreads();

    int b = blockIdx.x*128 + tid;
    const float4* a4 = (const float4*)&g_a1[b*16];
    float4 r0 = a4[0], r1 = a4[1], r2 = a4[2], r3 = a4[3];
    float a[16] = {r0.x,r0.y,r0.z,r0.w, r1.x,r1.y,r1.z,r1.w,
                   r2.x,r2.y,r2.z,r2.w, r3.x,r3.y,r3.z,r3.w};
    float z[32];
    #pragma unroll
    for (int o4 = 0; o4 < 8; ++o4) {
        float4 acc = make_float4(sc2[o4*4], sc2[o4*4+1], sc2[o4*4+2], sc2[o4*4+3]);
        #pragma unroll
        for (int i = 0; i < 16; ++i) {
            float4 w = sW4[i*8 + o4];
            acc.x += a[i]*w.x; acc.y += a[i]*w.y; acc.z += a[i]*w.z; acc.w += a[i]*w.w;
        }
        z[o4*4]   = fmaxf(acc.x, 0.f); z[o4*4+1] = fmaxf(acc.y, 0.f);
        z[o4*4+2] = fmaxf(acc.z, 0.f); z[o4*4+3] = fmaxf(acc.w, 0.f);
    }
    int lane = tid & 31;
    float mysum = 0.f, myss = 0.f;
    #pragma unroll
    for (int o = 0; o < 32; ++o) {
        float r = z[o], q = z[o]*z[o];
        #pragma unroll
        for (int sh = 16; sh > 0; sh >>= 1) {
            r += __shfl_xor_sync(0xffffffffu, r, sh);
            q += __shfl_xor_sync(0xffffffffu, q, sh);
        }
        if (lane == o) { mysum = r; myss = q; }
    }
    atomicAdd(&rsum[lane], mysum);
    atomicAdd(&rss[lane], myss);
    __syncthreads();
    if (tid < 32) { atomicAdd(&g_sum2[tid], rsum[tid]); atomicAdd(&g_ss2[tid], rss[tid]); }
}

// ---------------- fc3: recompute z from a1, BN2 fold, logits ----------------
__global__ void __launch_bounds__(128) fc3_kernel(float* __restrict__ out,
                                                  const float* __restrict__ fc2w,
                                                  const float* __restrict__ fc2b,
                                                  const float* __restrict__ g1,
                                                  const float* __restrict__ bb1,
                                                  const float* __restrict__ fc3w,
                                                  const float* __restrict__ fc3b,
                                                  const float* __restrict__ g2,
                                                  const float* __restrict__ bb2)
{
    __shared__ float sS[32], sOff[32];
    __shared__ float4 sW4[16*8];
    __shared__ float sc2[32];
    __shared__ float sW3[64], sc3[2];
    int tid = threadIdx.x;
    // BN1 fold into fc2
    if (tid < 16) {
        float m = g_sum1[tid] * (1.0f/NGRAPH);
        float v = g_ss1[tid] * (1.0f/NGRAPH) - m*m;
        float sc = rsqrtf(v + BN_EPS) * g1[tid];
        sS[tid] = sc; sOff[tid] = bb1[tid] - m*sc;
    }
    __syncthreads();
    float* sW = (float*)sW4;
    for (int i = tid; i < 512; i += 128) sW[i] = sS[i >> 5] * fc2w[i];
    if (tid < 32) {
        float c = fc2b[tid];
        #pragma unroll
        for (int r = 0; r < 16; ++r) c += sOff[r]*fc2w[r*32+tid];
        sc2[tid] = c;
    }
    __syncthreads();
    // BN2 fold into fc3 (reuse sS/sOff for 32-wide)
    if (tid < 32) {
        float m = g_sum2[tid] * (1.0f/NGRAPH);
        float v = g_ss2[tid] * (1.0f/NGRAPH) - m*m;
        float sc = rsqrtf(v + BN_EPS) * g2[tid];
        sS[tid] = sc; sOff[tid] = bb2[tid] - m*sc;
    }
    __syncthreads();
    if (tid < 64) sW3[tid] = sS[tid >> 1] * fc3w[tid];
    if (tid < 2) {
        float c = fc3b[tid];
        #pragma unroll
        for (int r = 0; r < 32; ++r) c += sOff[r]*fc3w[r*2+tid];
        sc3[tid] = c;
    }
    __syncthreads();

    int b = blockIdx.x*128 + tid;
    const float4* a4 = (const float4*)&g_a1[b*16];
    float4 r0 = a4[0], r1 = a4[1], r2 = a4[2], r3 = a4[3];
    float a[16] = {r0.x,r0.y,r0.z,r0.w, r1.x,r1.y,r1.z,r1.w,
                   r2.x,r2.y,r2.z,r2.w, r3.x,r3.y,r3.z,r3.w};
    float o0 = sc3[0], o1 = sc3[1];
    #pragma unroll
    for (int o4 = 0; o4 < 8; ++o4) {
        float4 acc = make_float4(sc2[o4*4], sc2[o4*4+1], sc2[o4*4+2], sc2[o4*4+3]);
        #pragma unroll
        for (int i = 0; i < 16; ++i) {
            float4 w = sW4[i*8 + o4];
            acc.x += a[i]*w.x; acc.y += a[i]*w.y; acc.z += a[i]*w.z; acc.w += a[i]*w.w;
        }
        acc.x = fmaxf(acc.x, 0.f); acc.y = fmaxf(acc.y, 0.f);
        acc.z = fmaxf(acc.z, 0.f); acc.w = fmaxf(acc.w, 0.f);
        o0 += acc.x*sW3[(o4*4+0)*2]   + acc.y*sW3[(o4*4+1)*2]
            + acc.z*sW3[(o4*4+2)*2]   + acc.w*sW3[(o4*4+3)*2];
        o1 += acc.x*sW3[(o4*4+0)*2+1] + acc.y*sW3[(o4*4+1)*2+1]
            + acc.z*sW3[(o4*4+2)*2+1] + acc.w*sW3[(o4*4+3)*2+1];
    }
    ((float2*)out)[b] = make_float2(o0, o1);
}

// ---------------- launch ----------------
extern "C" void kernel_launch(void* const* d_in, const int* in_sizes, int n_in,
                              void* d_out, int out_size)
{
    const float* x    = (const float*)d_in[0];
    const int*   ei   = (const int*)  d_in[1];
    const float* W11  = (const float*)d_in[2];
    const float* b11  = (const float*)d_in[3];
    const float* W21  = (const float*)d_in[4];
    const float* b21  = (const float*)d_in[5];
    const float* W12  = (const float*)d_in[6];
    const float* b12  = (const float*)d_in[7];
    const float* W22  = (const float*)d_in[8];
    const float* b22  = (const float*)d_in[9];
    const float* W13  = (const float*)d_in[10];
    const float* b13  = (const float*)d_in[11];
    const float* W23  = (const float*)d_in[12];
    const float* b23  = (const float*)d_in[13];
    const float* fc1w = (const float*)d_in[14];
    const float* fc1b = (const float*)d_in[15];
    const float* bn1g = (const float*)d_in[16];
    const float* bn1b = (const float*)d_in[17];
    const float* fc2w = (const float*)d_in[18];
    const float* fc2b = (const float*)d_in[19];
    const float* bn2g = (const float*)d_in[20];
    const float* bn2b = (const float*)d_in[21];
    const float* fc3w = (const float*)d_in[22];
    const float* fc3b = (const float*)d_in[23];

    prep_kernel<<<1, 256>>>(W11,b11,W21,b21,W12,b12,W22,b22,W13,b13,W23,b23,fc1w,fc1b);
    gcn_kernel<<<NGRAPH/(2*PAIRS), T1>>>(x, ei);
    fc2_kernel<<<NGRAPH/128, 128>>>(fc2w, fc2b, bn1g, bn1b);
    fc3_kernel<<<NGRAPH/128, 128>>>((float*)d_out, fc2w, fc2b, bn1g, bn1b,
                                    fc3w, fc3b, bn2g, bn2b);
}

// round 7
// speedup vs baseline: 1.9800x; 1.3288x over previous
#include <cuda_runtime.h>

typedef unsigned long long u64;
typedef unsigned int u32;

#define NPG 50
#define EPG 400
#define NGRAPH 32768
#define NNODE (NGRAPH*NPG)
#define NEDGE (NGRAPH*EPG)
#define WPC 8                 // warps per CTA in gcn
#define GPW 8                 // graphs per warp
#define T1 (WPC*32)
#define BN_EPS 1e-5f

#define FMA2(acc,a,b) asm("fma.rn.f32x2 %0,%1,%2,%0;" : "+l"(acc) : "l"(a), "l"(b))
#define ADD2(acc,a)   asm("add.rn.f32x2 %0,%1,%0;"    : "+l"(acc) : "l"(a))
__device__ __forceinline__ u64 packf2(float lo, float hi) {
    u64 r; asm("mov.b64 %0,{%1,%2};" : "=l"(r) : "r"(__float_as_uint(lo)), "r"(__float_as_uint(hi)));
    return r;
}
__device__ __forceinline__ float lo32(u64 v){ return __uint_as_float((unsigned)v); }
__device__ __forceinline__ float hi32(u64 v){ return __uint_as_float((unsigned)(v>>32)); }

// ---------------- device scratch (static; no allocation) ----------------
__device__ u64   g_GGc[NPG*16];    // interleaved (G, Gc) folded fc1 weights
__device__ float g_e1[16];
__device__ float g_sum1[16], g_ss1[16];
__device__ float g_sum2[32], g_ss2[32];
__device__ float g_a1[NGRAPH*16];  // 2 MB
__device__ float g_a2[NGRAPH*32];  // 4 MB

// ---------------- prep: fold W1k@W2k into fc1, zero accumulators ----------------
__global__ void prep_kernel(const float* __restrict__ W11, const float* __restrict__ b11,
                            const float* __restrict__ W21, const float* __restrict__ b21,
                            const float* __restrict__ W12, const float* __restrict__ b12,
                            const float* __restrict__ W22, const float* __restrict__ b22,
                            const float* __restrict__ W13, const float* __restrict__ b13,
                            const float* __restrict__ W23, const float* __restrict__ b23,
                            const float* __restrict__ fc1w, const float* __restrict__ fc1b)
{
    __shared__ float u[12], cv[12], dv[12];
    int tid = threadIdx.x;
    if (tid < 12) {
        int k = tid / 4, o = tid % 4;
        const float* W1 = (k==0) ? W11 : ((k==1) ? W12 : W13);
        const float* W2 = (k==0) ? W21 : ((k==1) ? W22 : W23);
        const float* b1 = (k==0) ? b11 : ((k==1) ? b12 : b13);
        const float* b2 = (k==0) ? b21 : ((k==1) ? b22 : b23);
        float uu = 0.f, cc = 0.f;
        #pragma unroll
        for (int m = 0; m < 4; ++m) { uu += W1[m]*W2[m*4+o]; cc += b1[m]*W2[m*4+o]; }
        u[tid] = uu; cv[tid] = cc; dv[tid] = b2[o];
    }
    __syncthreads();
    for (int i = tid; i < NPG*16; i += blockDim.x) {
        int j = i >> 4, o = i & 15;
        float gg = 0.f, gc = 0.f;
        #pragma unroll
        for (int f = 0; f < 12; ++f) {
            float w = fc1w[(j*12+f)*16 + o];
            gg += u[f]*w; gc += cv[f]*w;
        }
        g_GGc[i] = packf2(gg, gc);
    }
    if (tid < 16) {
        float e = fc1b[tid];
        for (int j = 0; j < NPG; ++j)
            #pragma unroll
            for (int f = 0; f < 12; ++f)
                e += dv[f]*fc1w[(j*12+f)*16 + tid];
        g_e1[tid] = e;
        g_sum1[tid] = 0.f; g_ss1[tid] = 0.f;
    }
    if (tid < 32) { g_sum2[tid] = 0.f; g_ss2[tid] = 0.f; }
}

// ---------------- main GCN kernel: warp-per-graph, bitmask adjacency ----------------
__global__ void __launch_bounds__(T1, 4) gcn_kernel(const float* __restrict__ x,
                                                    const int* __restrict__ ei)
{
    __shared__ u32  sMask[WPC][NPG*2];        // 64-bit row masks
    __shared__ float sAx[WPC][NPG];           // accumulate target (x-path / degree)
    __shared__ float sAr[WPC][NPG];           // accumulate target (ones-path)
    __shared__ u64  sWxd[WPC][NPG];           // packed (x*dinv, dinv)
    __shared__ float sW2[WPC][NPG];           // sweep-2 input
    __shared__ u64  sYR[WPC][NPG];            // packed (yv, rv)
    __shared__ unsigned short sDup[WPC][EPG]; // duplicate-edge list
    __shared__ int  sNdup[WPC];
    __shared__ u64  sGGc[NPG*16];             // interleaved fc1 weights
    __shared__ float se1[16];

    int tid = threadIdx.x, w = tid >> 5, lane = tid & 31;
    for (int i = tid; i < NPG*16; i += T1) sGGc[i] = g_GGc[i];
    if (tid < 16) se1[tid] = g_e1[tid];
    __syncthreads();

    u32*  mask = sMask[w];
    float* ax  = sAx[w];
    float* ar  = sAr[w];
    u64*  wxd  = sWxd[w];
    float* w2  = sW2[w];
    u64*  yr   = sYR[w];
    unsigned short* dup = sDup[w];

    const int r1 = lane, r2 = 32 + lane;
    const bool has2 = (lane < NPG - 32);
    float psum = 0.f, pss = 0.f;
    int gbase = (blockIdx.x * WPC + w) * GPW;

    for (int gi = 0; gi < GPW; ++gi) {
        int g = gbase + gi, nb = g*NPG, eb = g*EPG;
        // P0: zero ALL 100 mask words + load x
        float x1 = x[nb + r1];
        float x2 = has2 ? x[nb + r2] : 0.f;
        mask[lane] = 0; mask[32 + lane] = 0; mask[64 + lane] = 0;
        if (lane < 2*NPG - 96) mask[96 + lane] = 0;   // words 96..99 (rows 48,49)
        if (lane == 0) sNdup[w] = 0;
        __syncwarp();
        // P1: build bitmask adjacency; atomicOr detects duplicates
        #pragma unroll 4
        for (int e = lane; e < EPG; e += 32) {
            int s = ei[eb + e] - nb;
            int d = ei[NEDGE + eb + e] - nb;
            u32 bit = 1u << (s & 31);
            u32 old = atomicOr(&mask[d*2 + (s >> 5)], bit);
            if (old & bit) {
                int k = atomicAdd(&sNdup[w], 1);
                dup[k] = (unsigned short)(d*64 + s);
            }
        }
        __syncwarp();
        int nd = sNdup[w];
        // P2: degree = 1 + popcount (+ dup events)
        {
            ax[r1] = 1.f + (float)(__popc(mask[2*r1]) + __popc(mask[2*r1+1]));
            if (has2)
                ax[r2] = 1.f + (float)(__popc(mask[2*r2]) + __popc(mask[2*r2+1]));
        }
        __syncwarp();
        for (int k = lane; k < nd; k += 32) atomicAdd(&ax[dup[k] >> 6], 1.0f);
        __syncwarp();
        float di1 = rsqrtf(ax[r1]), di2 = 0.f;
        wxd[r1] = packf2(x1*di1, di1);
        if (has2) { di2 = rsqrtf(ax[r2]); wxd[r2] = packf2(x2*di2, di2); }
        __syncwarp();
        // P3: sweep 1 (x-path and ones-path packed in f32x2)
        {
            u64 a = wxd[r1];
            u32 m0 = mask[2*r1], m1 = mask[2*r1+1];
            while (m0) { int j = __ffs(m0)-1;  m0 &= m0-1; u64 v = wxd[j]; ADD2(a, v); }
            while (m1) { int j = __ffs(m1)+31; m1 &= m1-1; u64 v = wxd[j]; ADD2(a, v); }
            ax[r1] = lo32(a); ar[r1] = hi32(a);
            if (has2) {
                u64 b = wxd[r2];
                u32 n0 = mask[2*r2], n1 = mask[2*r2+1];
                while (n0) { int j = __ffs(n0)-1;  n0 &= n0-1; u64 v = wxd[j]; ADD2(b, v); }
                while (n1) { int j = __ffs(n1)+31; n1 &= n1-1; u64 v = wxd[j]; ADD2(b, v); }
                ax[r2] = lo32(b); ar[r2] = hi32(b);
            }
        }
        __syncwarp();
        for (int k = lane; k < nd; k += 32) {
            int c = dup[k]; u64 v = wxd[c & 63];
            atomicAdd(&ax[c >> 6], lo32(v));
            atomicAdd(&ar[c >> 6], hi32(v));
        }
        __syncwarp();
        float rv1 = ar[r1]*di1, rv2 = 0.f;
        w2[r1] = ax[r1]*di1*di1;
        if (has2) { rv2 = ar[r2]*di2; w2[r2] = ax[r2]*di2*di2; }
        __syncwarp();
        // P4: sweep 2 (scalar)
        {
            float a = w2[r1];
            u32 m0 = mask[2*r1], m1 = mask[2*r1+1];
            while (m0) { int j = __ffs(m0)-1;  m0 &= m0-1; a += w2[j]; }
            while (m1) { int j = __ffs(m1)+31; m1 &= m1-1; a += w2[j]; }
            ax[r1] = a;
            if (has2) {
                float b = w2[r2];
                u32 n0 = mask[2*r2], n1 = mask[2*r2+1];
                while (n0) { int j = __ffs(n0)-1;  n0 &= n0-1; b += w2[j]; }
                while (n1) { int j = __ffs(n1)+31; n1 &= n1-1; b += w2[j]; }
                ax[r2] = b;
            }
        }
        __syncwarp();
        for (int k = lane; k < nd; k += 32) {
            int c = dup[k];
            atomicAdd(&ax[c >> 6], w2[c & 63]);
        }
        __syncwarp();
        yr[r1] = packf2(ax[r1]*di1, rv1);
        if (has2) yr[r2] = packf2(ax[r2]*di2, rv2);
        __syncwarp();
        // P5: fc1 — a1[g,o] = e1[o] + Σ_j yv[j]G[j,o] + rv[j]Gc[j,o]
        {
            int o = lane & 15, half = lane >> 4;
            int j0 = half * 25;
            u64 acc = 0;
            #pragma unroll
            for (int j = 0; j < 25; ++j) {
                u64 y = yr[j0 + j];
                u64 gg = sGGc[(j0 + j)*16 + o];
                FMA2(acc, y, gg);
            }
            float s = lo32(acc) + hi32(acc);
            s += __shfl_down_sync(0xffffffffu, s, 16);
            if (lane < 16) {
                float a = fmaxf(se1[o] + s, 0.f);
                g_a1[g*16 + o] = a;
                psum += a; pss += a*a;
            }
        }
        __syncwarp();   // yr fully consumed before next graph overwrites shared state
    }
    if (lane < 16) { atomicAdd(&g_sum1[lane], psum); atomicAdd(&g_ss1[lane], pss); }
}

// ---------------- fc2: BN1 fold + GEMV + relu -> g_a2 + BN2 stats (transpose tile) ----------------
__global__ void __launch_bounds__(128) fc2_kernel(const float* __restrict__ fc2w,
                                                  const float* __restrict__ fc2b,
                                                  const float* __restrict__ g1,
                                                  const float* __restrict__ bb1)
{
    __shared__ float sS[16], sOff[16];
    __shared__ float4 sW4[16*8];
    __shared__ float sc2[32];
    __shared__ float tile[4][32][33];
    __shared__ float rsum[32], rss[32];
    int tid = threadIdx.x, lane = tid & 31, w = tid >> 5;
    if (tid < 16) {
        float m = g_sum1[tid] * (1.0f/NGRAPH);
        float v = g_ss1[tid] * (1.0f/NGRAPH) - m*m;
        float sc = rsqrtf(v + BN_EPS) * g1[tid];
        sS[tid] = sc; sOff[tid] = bb1[tid] - m*sc;
    }
    if (tid < 32) { rsum[tid] = 0.f; rss[tid] = 0.f; }
    __syncthreads();
    float* sW = (float*)sW4;
    for (int i = tid; i < 512; i += 128) sW[i] = sS[i >> 5] * fc2w[i];
    if (tid < 32) {
        float c = fc2b[tid];
        #pragma unroll
        for (int r = 0; r < 16; ++r) c += sOff[r]*fc2w[r*32+tid];
        sc2[tid] = c;
    }
    __syncthreads();

    int b = blockIdx.x*128 + tid;
    const float4* a4 = (const float4*)&g_a1[b*16];
    float4 r0 = a4[0], r1 = a4[1], r2 = a4[2], r3 = a4[3];
    float a[16] = {r0.x,r0.y,r0.z,r0.w, r1.x,r1.y,r1.z,r1.w,
                   r2.x,r2.y,r2.z,r2.w, r3.x,r3.y,r3.z,r3.w};
    float4* out4 = (float4*)&g_a2[b*32];
    #pragma unroll
    for (int o4 = 0; o4 < 8; ++o4) {
        float4 acc = make_float4(sc2[o4*4], sc2[o4*4+1], sc2[o4*4+2], sc2[o4*4+3]);
        #pragma unroll
        for (int i = 0; i < 16; ++i) {
            float4 ww = sW4[i*8 + o4];
            acc.x += a[i]*ww.x; acc.y += a[i]*ww.y; acc.z += a[i]*ww.z; acc.w += a[i]*ww.w;
        }
        acc.x = fmaxf(acc.x, 0.f); acc.y = fmaxf(acc.y, 0.f);
        acc.z = fmaxf(acc.z, 0.f); acc.w = fmaxf(acc.w, 0.f);
        out4[o4] = acc;
        tile[w][lane][o4*4]   = acc.x; tile[w][lane][o4*4+1] = acc.y;
        tile[w][lane][o4*4+2] = acc.z; tile[w][lane][o4*4+3] = acc.w;
    }
    __syncwarp();
    float s = 0.f, ss = 0.f;
    #pragma unroll
    for (int j = 0; j < 32; ++j) {
        float v = tile[w][j][lane];
        s += v; ss += v*v;
    }
    atomicAdd(&rsum[lane], s);
    atomicAdd(&rss[lane], ss);
    __syncthreads();
    if (tid < 32) { atomicAdd(&g_sum2[tid], rsum[tid]); atomicAdd(&g_ss2[tid], rss[tid]); }
}

// ---------------- fc3: in-block BN2 fold + final logits (reads g_a2) ----------------
__global__ void __launch_bounds__(128) fc3_kernel(float* __restrict__ out,
                                                  const float* __restrict__ fc3w,
                                                  const float* __restrict__ fc3b,
                                                  const float* __restrict__ g2,
                                                  const float* __restrict__ bb2)
{
    __shared__ float sS[32], sOff[32], sW[64], sc3[2];
    int tid = threadIdx.x;
    if (tid < 32) {
        float m = g_sum2[tid] * (1.0f/NGRAPH);
        float v = g_ss2[tid] * (1.0f/NGRAPH) - m*m;
        float sc = rsqrtf(v + BN_EPS) * g2[tid];
        sS[tid] = sc; sOff[tid] = bb2[tid] - m*sc;
    }
    __syncthreads();
    if (tid < 64) sW[tid] = sS[tid >> 1] * fc3w[tid];
    if (tid < 2) {
        float c = fc3b[tid];
        #pragma unroll
        for (int r = 0; r < 32; ++r) c += sOff[r]*fc3w[r*2+tid];
        sc3[tid] = c;
    }
    __syncthreads();
    int b = blockIdx.x*128 + tid;
    const float4* a2r = (const float4*)&g_a2[b*32];
    float o0 = sc3[0], o1 = sc3[1];
    #pragma unroll
    for (int q = 0; q < 8; ++q) {
        float4 v = a2r[q];
        o0 += v.x*sW[(q*4+0)*2]   + v.y*sW[(q*4+1)*2]   + v.z*sW[(q*4+2)*2]   + v.w*sW[(q*4+3)*2];
        o1 += v.x*sW[(q*4+0)*2+1] + v.y*sW[(q*4+1)*2+1] + v.z*sW[(q*4+2)*2+1] + v.w*sW[(q*4+3)*2+1];
    }
    ((float2*)out)[b] = make_float2(o0, o1);
}

// ---------------- launch ----------------
extern "C" void kernel_launch(void* const* d_in, const int* in_sizes, int n_in,
                              void* d_out, int out_size)
{
    const float* x    = (const float*)d_in[0];
    const int*   ei   = (const int*)  d_in[1];
    const float* W11  = (const float*)d_in[2];
    const float* b11  = (const float*)d_in[3];
    const float* W21  = (const float*)d_in[4];
    const float* b21  = (const float*)d_in[5];
    const float* W12  = (const float*)d_in[6];
    const float* b12  = (const float*)d_in[7];
    const float* W22  = (const float*)d_in[8];
    const float* b22  = (const float*)d_in[9];
    const float* W13  = (const float*)d_in[10];
    const float* b13  = (const float*)d_in[11];
    const float* W23  = (const float*)d_in[12];
    const float* b23  = (const float*)d_in[13];
    const float* fc1w = (const float*)d_in[14];
    const float* fc1b = (const float*)d_in[15];
    const float* bn1g = (const float*)d_in[16];
    const float* bn1b = (const float*)d_in[17];
    const float* fc2w = (const float*)d_in[18];
    const float* fc2b = (const float*)d_in[19];
    const float* bn2g = (const float*)d_in[20];
    const float* bn2b = (const float*)d_in[21];
    const float* fc3w = (const float*)d_in[22];
    const float* fc3b = (const float*)d_in[23];

    prep_kernel<<<1, 256>>>(W11,b11,W21,b21,W12,b12,W22,b22,W13,b13,W23,b23,fc1w,fc1b);
    gcn_kernel<<<NGRAPH/(WPC*GPW), T1>>>(x, ei);
    fc2_kernel<<<NGRAPH/128, 128>>>(fc2w, fc2b, bn1g, bn1b);
    fc3_kernel<<<NGRAPH/128, 128>>>((float*)d_out, fc3w, fc3b, bn2g, bn2b);
}